// round 1
// baseline (speedup 1.0000x reference)
#include <cuda_runtime.h>
#include <cuda_bf16.h>
#include <math.h>

// ---------------------------------------------------------------------------
// DiscriptorMatchLoss: sparse-mask cosine matching loss.
//   features [B,N,D] f32, pts_src [B,N,2] f32, pts_dst [B,B,N,2] f32,
//   invis_idx (unused), height, width (int scalars).
//   out[0] = sum_{mask} (1 - cos(f[j,n], f[i,m])) / max(count,1)
//   mask[i,j,n,m] = ||denorm(ps[i,n]) - denorm(pd[i,j,m])||^2 <= 64
// Mask hit rate ~6.5e-4 -> only ~44k of 67M pairs need a dot product.
// ---------------------------------------------------------------------------

#define MAX_ROWS (1 << 16)

__device__ float g_invnorm[MAX_ROWS];
__device__ double g_sum;
__device__ unsigned long long g_cnt;

// Kernel 1: per-row inverse norms (one warp per [b,n] row) + zero accumulators.
__global__ void k_norms(const float* __restrict__ f, int rows, int D) {
    if (blockIdx.x == 0 && threadIdx.x == 0) { g_sum = 0.0; g_cnt = 0ULL; }
    int w    = (blockIdx.x * blockDim.x + threadIdx.x) >> 5;
    int lane = threadIdx.x & 31;
    if (w >= rows) return;
    const float* row = f + (size_t)w * D;
    float s = 0.f;
    for (int d = lane; d < D; d += 32) { float v = row[d]; s += v * v; }
    #pragma unroll
    for (int o = 16; o; o >>= 1) s += __shfl_xor_sync(0xffffffffu, s, o);
    if (lane == 0) g_invnorm[w] = 1.0f / sqrtf(s);
}

// Kernel 2: one warp per (i,j,n). Lanes sweep m; ballot collects the sparse
// hits; warp cooperatively computes each hit's D-dim dot product.
__global__ void __launch_bounds__(256)
k_main(const float* __restrict__ f,
       const float* __restrict__ ps,
       const float* __restrict__ pd,
       const int* __restrict__ hp,
       const int* __restrict__ wp,
       int B, int N, int D) {
    int gw   = (blockIdx.x * blockDim.x + threadIdx.x) >> 5;
    int lane = threadIdx.x & 31;
    int total = B * B * N;
    if (gw >= total) return;

    int n  = gw % N;
    int ij = gw / N;
    int j  = ij % B;
    int i  = ij / B;

    const float sx = 0.5f * (float)(wp[0] - 1);
    const float sy = 0.5f * (float)(hp[0] - 1);

    const float psx = (ps[((size_t)i * N + n) * 2 + 0] + 1.0f) * sx;
    const float psy = (ps[((size_t)i * N + n) * 2 + 1] + 1.0f) * sy;

    // Cache src feature row f[j,n] across the warp: 8 regs/lane, stride-32.
    const float* fa = f + ((size_t)j * N + n) * D;
    float a[8];
    #pragma unroll
    for (int k = 0; k < 8; k++) {
        int d = lane + 32 * k;
        a[k] = (d < D) ? fa[d] : 0.0f;
    }
    const float invn_jn = g_invnorm[j * N + n];

    const float* pdr = pd + ((size_t)(i * B + j)) * N * 2;

    float    lsum = 0.0f;
    unsigned lcnt = 0;

    for (int base = 0; base < N; base += 32) {
        int m0 = base + lane;
        int mm = m0 < N ? m0 : N - 1;
        float dx = (pdr[(size_t)mm * 2 + 0] + 1.0f) * sx - psx;
        float dy = (pdr[(size_t)mm * 2 + 1] + 1.0f) * sy - psy;
        bool pred = (m0 < N) && (dx * dx + dy * dy <= 64.0f);
        unsigned bits = __ballot_sync(0xffffffffu, pred);
        while (bits) {
            int bit = __ffs(bits) - 1;
            bits &= bits - 1;
            int m = base + bit;
            const float* fb = f + ((size_t)i * N + m) * D;
            float dot = 0.0f;
            #pragma unroll
            for (int k = 0; k < 8; k++) {
                int d = lane + 32 * k;
                if (d < D) dot += a[k] * fb[d];
            }
            #pragma unroll
            for (int o = 16; o; o >>= 1) dot += __shfl_xor_sync(0xffffffffu, dot, o);
            if (lane == 0) {
                float inv_denom = invn_jn * g_invnorm[i * N + m];
                lsum += 1.0f - dot * inv_denom;
                lcnt++;
            }
        }
    }

    if (lane == 0 && lcnt) {
        atomicAdd(&g_sum, (double)lsum);
        atomicAdd(&g_cnt, (unsigned long long)lcnt);
    }
}

// Kernel 3: finalize.
__global__ void k_final(float* __restrict__ out) {
    unsigned long long c = g_cnt;
    if (c == 0ULL) c = 1ULL;
    out[0] = (float)(g_sum / (double)c);
}

extern "C" void kernel_launch(void* const* d_in, const int* in_sizes, int n_in,
                              void* d_out, int out_size) {
    const float* features = (const float*)d_in[0];
    const float* pts_src  = (const float*)d_in[1];
    const float* pts_dst  = (const float*)d_in[2];
    // d_in[3] = invis_idx (unused by the reference)
    const int* hp = (const int*)d_in[4];
    const int* wp = (const int*)d_in[5];
    float* out = (float*)d_out;

    // Derive shapes: sizes[1] = B*N*2, sizes[2] = B*B*N*2, sizes[0] = B*N*D
    int B = in_sizes[2] / in_sizes[1];
    int N = in_sizes[1] / (2 * B);
    int D = in_sizes[0] / (B * N);
    int rows = B * N;

    {
        int threads = 256;
        int blocks = (rows * 32 + threads - 1) / threads;
        k_norms<<<blocks, threads>>>(features, rows, D);
    }
    {
        int total_warps = B * B * N;
        int threads = 256;
        int blocks = ((long long)total_warps * 32 + threads - 1) / threads;
        k_main<<<blocks, threads>>>(features, pts_src, pts_dst, hp, wp, B, N, D);
    }
    k_final<<<1, 1>>>(out);
    (void)n_in; (void)out_size; (void)in_sizes;
}

// round 2
// speedup vs baseline: 3.2563x; 3.2563x over previous
#include <cuda_runtime.h>
#include <cuda_bf16.h>
#include <math.h>

// ---------------------------------------------------------------------------
// DiscriptorMatchLoss — sparse cosine matching loss via spatial hashing.
//   mask[i,j,n,m] = ||denorm(ps[i,n]) - denorm(pd[i,j,m])||^2 <= 64
//   out = sum_mask (1 - cos(f[j,n], f[i,m])) / max(count,1)
// Hit rate ~6.5e-4 -> grid-bin dst points (16px cells), each src point checks
// a 2x2 cell neighborhood (~7 candidates) instead of all N=2048.
// ---------------------------------------------------------------------------

#define MAX_ROWS  (1 << 16)
#define MAXC      4096          // max grid cells per (i,j) pair
#define MAXN      4096          // max points per pair
#define MAXIJ     64            // max B*B
#define MAX_PAIRS (1 << 22)     // 4M hit pairs (expected ~44k)
#define RAD2      64.0f

__device__ float    g_invnorm[MAX_ROWS];
__device__ double   g_sum;
__device__ int      g_npairs;
__device__ int      g_cell_start[MAXIJ * (MAXC + 1)];
__device__ float2   g_bpts[MAXIJ * MAXN];
__device__ int      g_bidx[MAXIJ * MAXN];
__device__ unsigned g_pairs[MAX_PAIRS];

// ---------------- Kernel 1: row inverse-norms (float4) + zero accumulators --
__global__ void k_norms(const float* __restrict__ f, int rows, int D) {
    if (blockIdx.x == 0 && threadIdx.x == 0) { g_sum = 0.0; g_npairs = 0; }
    int w    = (blockIdx.x * blockDim.x + threadIdx.x) >> 5;
    int lane = threadIdx.x & 31;
    if (w >= rows) return;
    float s = 0.f;
    if ((D & 3) == 0) {
        const float4* row = (const float4*)(f + (size_t)w * D);
        int D4 = D >> 2;
        for (int d = lane; d < D4; d += 32) {
            float4 v = row[d];
            s += v.x * v.x + v.y * v.y + v.z * v.z + v.w * v.w;
        }
    } else {
        const float* row = f + (size_t)w * D;
        for (int d = lane; d < D; d += 32) { float v = row[d]; s += v * v; }
    }
    #pragma unroll
    for (int o = 16; o; o >>= 1) s += __shfl_xor_sync(0xffffffffu, s, o);
    if (lane == 0) g_invnorm[w] = rsqrtf(s);
}

// ---------------- Kernel 2: bin dst points into 16px cells (1 CTA per ij) --
__global__ void __launch_bounds__(256)
k_bin(const float* __restrict__ pd, const int* __restrict__ hp,
      const int* __restrict__ wp, int N) {
    __shared__ int s_start[MAXC + 1];
    __shared__ int s_cur[MAXC];
    __shared__ int s_part[256];

    int ij  = blockIdx.x;
    int tid = threadIdx.x;
    int W = wp[0], H = hp[0];
    int ncx = ((W - 1) >> 4) + 1;
    int ncy = ((H - 1) >> 4) + 1;
    int ncells = ncx * ncy;
    if (ncells > MAXC) ncells = MAXC;

    for (int c = tid; c <= ncells; c += 256) s_start[c] = 0;
    __syncthreads();

    const float sx = 0.5f * (float)(W - 1);
    const float sy = 0.5f * (float)(H - 1);
    const float* pdr = pd + (size_t)ij * N * 2;

    for (int m = tid; m < N; m += 256) {
        float x = (pdr[(size_t)m * 2 + 0] + 1.0f) * sx;
        float y = (pdr[(size_t)m * 2 + 1] + 1.0f) * sy;
        int cx = min(ncx - 1, max(0, (int)(x * 0.0625f)));
        int cy = min(ncy - 1, max(0, (int)(y * 0.0625f)));
        int cell = min(ncells - 1, cy * ncx + cx);
        atomicAdd(&s_start[cell], 1);
    }
    __syncthreads();

    // block exclusive scan over ncells
    int chunk = (ncells + 255) / 256;
    int base = tid * chunk;
    int sum = 0;
    for (int k = 0; k < chunk; k++) {
        int c = base + k;
        if (c < ncells) sum += s_start[c];
    }
    s_part[tid] = sum;
    __syncthreads();
    if (tid == 0) {
        int acc = 0;
        for (int t = 0; t < 256; t++) { int v = s_part[t]; s_part[t] = acc; acc += v; }
    }
    __syncthreads();
    {
        int acc = s_part[tid];
        for (int k = 0; k < chunk; k++) {
            int c = base + k;
            if (c < ncells) {
                int v = s_start[c];
                s_start[c] = acc;
                s_cur[c] = acc;
                acc += v;
            }
        }
    }
    __syncthreads();
    if (tid == 0) s_start[ncells] = N;

    // scatter
    for (int m = tid; m < N; m += 256) {
        float x = (pdr[(size_t)m * 2 + 0] + 1.0f) * sx;
        float y = (pdr[(size_t)m * 2 + 1] + 1.0f) * sy;
        int cx = min(ncx - 1, max(0, (int)(x * 0.0625f)));
        int cy = min(ncy - 1, max(0, (int)(y * 0.0625f)));
        int cell = min(ncells - 1, cy * ncx + cx);
        int pos = atomicAdd(&s_cur[cell], 1);
        g_bpts[(size_t)ij * MAXN + pos] = make_float2(x, y);
        g_bidx[(size_t)ij * MAXN + pos] = m;
    }
    __syncthreads();
    for (int c = tid; c <= ncells; c += 256)
        g_cell_start[(size_t)ij * (MAXC + 1) + c] = s_start[c];
}

// ---------------- Kernel 3: find hit pairs (1 thread per (i,j,n)) ----------
__global__ void __launch_bounds__(256)
k_match(const float* __restrict__ ps, const int* __restrict__ hp,
        const int* __restrict__ wp, int B, int N) {
    int t    = blockIdx.x * blockDim.x + threadIdx.x;
    int lane = threadIdx.x & 31;
    int total = B * B * N;

    unsigned hits[32];
    int hc = 0;

    if (t < total) {
        int n  = t % N;
        int ij = t / N;
        int i  = ij / B;

        int W = wp[0], H = hp[0];
        int ncx = ((W - 1) >> 4) + 1;
        int ncy = ((H - 1) >> 4) + 1;
        int ncells = ncx * ncy;
        if (ncells > MAXC) ncells = MAXC;

        const float sx = 0.5f * (float)(W - 1);
        const float sy = 0.5f * (float)(H - 1);
        float x = (ps[((size_t)i * N + n) * 2 + 0] + 1.0f) * sx;
        float y = (ps[((size_t)i * N + n) * 2 + 1] + 1.0f) * sy;

        int cx0 = max(0, (int)floorf((x - 8.0f) * 0.0625f));
        int cx1 = min(ncx - 1, (int)floorf((x + 8.0f) * 0.0625f));
        int cy0 = max(0, (int)floorf((y - 8.0f) * 0.0625f));
        int cy1 = min(ncy - 1, (int)floorf((y + 8.0f) * 0.0625f));

        const int*    cs = g_cell_start + (size_t)ij * (MAXC + 1);
        const float2* bp = g_bpts + (size_t)ij * MAXN;
        const int*    bi = g_bidx + (size_t)ij * MAXN;

        for (int cy = cy0; cy <= cy1; cy++) {
            for (int cx = cx0; cx <= cx1; cx++) {
                int cell = cy * ncx + cx;
                int s = cs[cell], e = cs[cell + 1];
                for (int k = s; k < e; k++) {
                    float2 p = bp[k];
                    float dx = p.x - x, dy = p.y - y;
                    if (dx * dx + dy * dy <= RAD2) {
                        unsigned pk = ((unsigned)ij << 24) |
                                      ((unsigned)n << 12) | (unsigned)bi[k];
                        if (hc < 32) hits[hc++] = pk;
                        else {
                            int pos = atomicAdd(&g_npairs, 1);
                            if (pos < MAX_PAIRS) g_pairs[pos] = pk;
                        }
                    }
                }
            }
        }
    }

    // warp-aggregated append
    int pre = hc;
    #pragma unroll
    for (int o = 1; o < 32; o <<= 1) {
        int v = __shfl_up_sync(0xffffffffu, pre, o);
        if (lane >= o) pre += v;
    }
    int tot  = __shfl_sync(0xffffffffu, pre, 31);
    int excl = pre - hc;
    if (tot > 0) {
        int base = 0;
        if (lane == 31) base = atomicAdd(&g_npairs, tot);
        base = __shfl_sync(0xffffffffu, base, 31);
        for (int k = 0; k < hc; k++) {
            int pos = base + excl + k;
            if (pos < MAX_PAIRS) g_pairs[pos] = hits[k];
        }
    }
}

// ---------------- Kernel 4: dot products (1 warp per hit pair) -------------
__global__ void __launch_bounds__(256)
k_dot(const float* __restrict__ f, int B, int N, int D) {
    int gw    = (blockIdx.x * blockDim.x + threadIdx.x) >> 5;
    int lane  = threadIdx.x & 31;
    int nwarp = (gridDim.x * blockDim.x) >> 5;

    int np = g_npairs;
    if (np > MAX_PAIRS) np = MAX_PAIRS;

    double lsum = 0.0;
    int D4 = D >> 2;

    for (int p = gw; p < np; p += nwarp) {
        unsigned pk = g_pairs[p];
        int ij = pk >> 24;
        int n  = (pk >> 12) & 0xFFF;
        int m  = pk & 0xFFF;
        int i  = ij / B;
        int j  = ij % B;

        const float4* fa = (const float4*)(f + ((size_t)j * N + n) * D);
        const float4* fb = (const float4*)(f + ((size_t)i * N + m) * D);
        float dot = 0.f;
        for (int d = lane; d < D4; d += 32) {
            float4 a = fa[d], b = fb[d];
            dot += a.x * b.x + a.y * b.y + a.z * b.z + a.w * b.w;
        }
        #pragma unroll
        for (int o = 16; o; o >>= 1) dot += __shfl_xor_sync(0xffffffffu, dot, o);
        if (lane == 0)
            lsum += (double)(1.0f - dot * g_invnorm[j * N + n] * g_invnorm[i * N + m]);
    }
    if (lane == 0 && lsum != 0.0) atomicAdd(&g_sum, lsum);
}

// ---------------- Kernel 5: finalize ---------------------------------------
__global__ void k_final(float* __restrict__ out) {
    int c = g_npairs;
    if (c < 1) c = 1;
    out[0] = (float)(g_sum / (double)c);
}

extern "C" void kernel_launch(void* const* d_in, const int* in_sizes, int n_in,
                              void* d_out, int out_size) {
    const float* features = (const float*)d_in[0];
    const float* pts_src  = (const float*)d_in[1];
    const float* pts_dst  = (const float*)d_in[2];
    const int* hp = (const int*)d_in[4];
    const int* wp = (const int*)d_in[5];
    float* out = (float*)d_out;

    int B = in_sizes[2] / in_sizes[1];
    int N = in_sizes[1] / (2 * B);
    int D = in_sizes[0] / (B * N);
    int rows = B * N;

    {
        int blocks = (rows * 32 + 255) / 256;
        k_norms<<<blocks, 256>>>(features, rows, D);
    }
    k_bin<<<B * B, 256>>>(pts_dst, hp, wp, N);
    {
        int blocks = (B * B * N + 255) / 256;
        k_match<<<blocks, 256>>>(pts_src, hp, wp, B, N);
    }
    k_dot<<<512, 256>>>(features, B, N, D);
    k_final<<<1, 1>>>(out);
    (void)n_in; (void)out_size;
}